// round 1
// baseline (speedup 1.0000x reference)
#include <cuda_runtime.h>

#define NQ   2048
#define ND   100000
#define DIM  128
#define KSEL 10
#define BM   128
#define BN   128
#define KC   32
#define SPAD 132   // padded smem row (floats) to break STS bank conflicts

// Scratch (static __device__ arrays: the sanctioned no-alloc workaround)
__device__ float g_q2[NQ];
__device__ float g_x2w[ND];                 // ||x_n||^2 - w[n]
__device__ float g_s[(size_t)NQ * ND];      // score matrix s[b,n]

__device__ __forceinline__ unsigned long long dup2(float a) {
    unsigned long long d;
    asm("mov.b64 %0, {%1, %1};" : "=l"(d) : "r"(__float_as_uint(a)));
    return d;
}
__device__ __forceinline__ void ffma2(unsigned long long &c,
                                      unsigned long long a,
                                      unsigned long long b) {
    // packed 2x fp32 FMA (FFMA2) — sm_100+/sm_103a, only reachable via PTX
    asm("fma.rn.f32x2 %0, %1, %2, %0;" : "+l"(c) : "l"(a), "l"(b));
}

// ---------------------------------------------------------------------------
// Kernel 1: row norms. One warp per row.
//   g_x2w[n] = sum_k X[n,k]^2 - w[n]      (n < ND)
//   g_q2[b]  = sum_k q[b,k]^2             (b < NQ)
// ---------------------------------------------------------------------------
__global__ void prep_kernel(const float* __restrict__ X,
                            const float* __restrict__ w,
                            const float* __restrict__ q) {
    int gw   = (blockIdx.x * 256 + threadIdx.x) >> 5;
    int lane = threadIdx.x & 31;
    if (gw < ND) {
        float4 v = reinterpret_cast<const float4*>(X + (size_t)gw * DIM)[lane];
        float s = v.x * v.x + v.y * v.y + v.z * v.z + v.w * v.w;
        #pragma unroll
        for (int o = 16; o > 0; o >>= 1) s += __shfl_xor_sync(0xffffffffu, s, o);
        if (lane == 0) g_x2w[gw] = s - w[gw];
    } else if (gw < ND + NQ) {
        int r = gw - ND;
        float4 v = reinterpret_cast<const float4*>(q + (size_t)r * DIM)[lane];
        float s = v.x * v.x + v.y * v.y + v.z * v.z + v.w * v.w;
        #pragma unroll
        for (int o = 16; o > 0; o >>= 1) s += __shfl_xor_sync(0xffffffffu, s, o);
        if (lane == 0) g_q2[r] = s;
    }
}

// ---------------------------------------------------------------------------
// Kernel 2: score GEMM.  s[b,n] = -2 * dot(q_b, x_n) + g_x2w[n]
// 128x128 tile, 256 threads, 8x8 per thread, fp32x2 packed FMA.
// Register-prefetched K-chunks of 32.
// ---------------------------------------------------------------------------
__global__ __launch_bounds__(256, 1)
void gemm_kernel(const float* __restrict__ q, const float* __restrict__ X) {
    __shared__ float As[KC][SPAD];
    __shared__ float Bs[KC][SPAD];
    const int m0 = blockIdx.x * BM;   // m-tiles fastest -> n-tile shared in L2
    const int n0 = blockIdx.y * BN;
    const int t  = threadIdx.x;
    const int tx = t & 15, ty = t >> 4;

    unsigned long long acc[8][4];
    #pragma unroll
    for (int i = 0; i < 8; i++)
        #pragma unroll
        for (int j = 0; j < 4; j++) acc[i][j] = 0ull;

    float4 pa[4], pb[4];
    // prefetch chunk 0
    #pragma unroll
    for (int i = 0; i < 4; i++) {
        int id = t + 256 * i;
        int row = id >> 3, c4 = id & 7;
        pa[i] = *reinterpret_cast<const float4*>(q + (size_t)(m0 + row) * DIM + c4 * 4);
        int gn = n0 + row; if (gn >= ND) gn = ND - 1;   // clamp; edge cols never stored
        pb[i] = *reinterpret_cast<const float4*>(X + (size_t)gn * DIM + c4 * 4);
    }

    #pragma unroll 1
    for (int c = 0; c < DIM / KC; c++) {
        #pragma unroll
        for (int i = 0; i < 4; i++) {
            int id = t + 256 * i;
            int row = id >> 3, c4 = id & 7;
            As[c4 * 4 + 0][row] = pa[i].x; As[c4 * 4 + 1][row] = pa[i].y;
            As[c4 * 4 + 2][row] = pa[i].z; As[c4 * 4 + 3][row] = pa[i].w;
            Bs[c4 * 4 + 0][row] = pb[i].x; Bs[c4 * 4 + 1][row] = pb[i].y;
            Bs[c4 * 4 + 2][row] = pb[i].z; Bs[c4 * 4 + 3][row] = pb[i].w;
        }
        __syncthreads();
        if (c < DIM / KC - 1) {
            int kc = (c + 1) * KC;
            #pragma unroll
            for (int i = 0; i < 4; i++) {
                int id = t + 256 * i;
                int row = id >> 3, c4 = id & 7;
                pa[i] = *reinterpret_cast<const float4*>(q + (size_t)(m0 + row) * DIM + kc + c4 * 4);
                int gn = n0 + row; if (gn >= ND) gn = ND - 1;
                pb[i] = *reinterpret_cast<const float4*>(X + (size_t)gn * DIM + kc + c4 * 4);
            }
        }
        #pragma unroll
        for (int k = 0; k < KC; k++) {
            float4 a0 = *reinterpret_cast<const float4*>(&As[k][ty * 4]);
            float4 a1 = *reinterpret_cast<const float4*>(&As[k][ty * 4 + 64]);
            ulonglong2 b01 = *reinterpret_cast<const ulonglong2*>(&Bs[k][tx * 4]);
            ulonglong2 b23 = *reinterpret_cast<const ulonglong2*>(&Bs[k][tx * 4 + 64]);
            unsigned long long da[8];
            da[0] = dup2(a0.x); da[1] = dup2(a0.y); da[2] = dup2(a0.z); da[3] = dup2(a0.w);
            da[4] = dup2(a1.x); da[5] = dup2(a1.y); da[6] = dup2(a1.z); da[7] = dup2(a1.w);
            unsigned long long bp0 = b01.x, bp1 = b01.y, bp2 = b23.x, bp3 = b23.y;
            #pragma unroll
            for (int i = 0; i < 8; i++) {
                ffma2(acc[i][0], da[i], bp0);
                ffma2(acc[i][1], da[i], bp1);
                ffma2(acc[i][2], da[i], bp2);
                ffma2(acc[i][3], da[i], bp3);
            }
        }
        __syncthreads();
    }

    // epilogue: s = -2*dot + x2w, store pairwise
    #pragma unroll
    for (int i = 0; i < 8; i++) {
        int m = m0 + ty * 4 + (i & 3) + (i >> 2) * 64;
        #pragma unroll
        for (int j = 0; j < 4; j++) {
            int n = n0 + tx * 4 + (j & 1) * 2 + (j >> 1) * 64;
            if (n < ND) {
                float lo = __uint_as_float((unsigned)(acc[i][j] & 0xffffffffull));
                float hi = __uint_as_float((unsigned)(acc[i][j] >> 32));
                float2 sv;
                sv.x = fmaf(-2.0f, lo, g_x2w[n]);
                sv.y = fmaf(-2.0f, hi, g_x2w[n + 1]);
                *reinterpret_cast<float2*>(&g_s[(size_t)m * ND + n]) = sv;
            }
        }
    }
}

// ---------------------------------------------------------------------------
// Kernel 3: per-query top-10 (smallest s) + final activation argmax.
// One CTA per query; per-thread register top-10 then block 10-way merge.
// ---------------------------------------------------------------------------
__global__ __launch_bounds__(256, 1)
void select_kernel(const float* __restrict__ w, float* __restrict__ out) {
    const int b = blockIdx.x;
    const int t = threadIdx.x;
    const float4* row4 = reinterpret_cast<const float4*>(g_s + (size_t)b * ND);

    float bv[KSEL];
    int   bi[KSEL];
    #pragma unroll
    for (int r = 0; r < KSEL; r++) { bv[r] = __int_as_float(0x7f800000); bi[r] = 0; }

    for (int j4 = t; j4 < ND / 4; j4 += 256) {
        float4 v = row4[j4];
        int n = j4 * 4;
        float vv[4] = {v.x, v.y, v.z, v.w};
        #pragma unroll
        for (int ci4 = 0; ci4 < 4; ci4++) {
            float x = vv[ci4];
            if (x < bv[KSEL - 1]) {
                float cv = x; int ci = n + ci4;
                #pragma unroll
                for (int r = 0; r < KSEL; r++) {
                    if (cv < bv[r]) {
                        float tv = bv[r]; bv[r] = cv; cv = tv;
                        int ti = bi[r]; bi[r] = ci; ci = ti;
                    }
                }
            }
        }
    }

    __shared__ float sv[256 * (KSEL + 1)];
    __shared__ int   si[256 * (KSEL + 1)];
    __shared__ float redv[256];
    __shared__ int   redt[256];
    __shared__ float selv[KSEL];
    __shared__ int   seli[KSEL];

    #pragma unroll
    for (int r = 0; r < KSEL; r++) {
        sv[t * (KSEL + 1) + r] = bv[r];
        si[t * (KSEL + 1) + r] = bi[r];
    }
    sv[t * (KSEL + 1) + KSEL] = __int_as_float(0x7f800000);  // sentinel
    __syncthreads();

    int h = 0;
    for (int r = 0; r < KSEL; r++) {
        redv[t] = sv[t * (KSEL + 1) + h];
        redt[t] = t;
        __syncthreads();
        #pragma unroll
        for (int s = 128; s > 0; s >>= 1) {
            if (t < s) {
                if (redv[t + s] < redv[t]) { redv[t] = redv[t + s]; redt[t] = redt[t + s]; }
            }
            __syncthreads();
        }
        if (t == redt[0]) {
            selv[r] = sv[t * (KSEL + 1) + h];
            seli[r] = si[t * (KSEL + 1) + h];
            h++;
        }
        __syncthreads();
    }

    if (t == 0) {
        float q2 = g_q2[b];
        float bestf = __int_as_float(0xff800000);  // -inf
        int besti = 0;
        #pragma unroll
        for (int r = 0; r < KSEL; r++) {
            int idx = seli[r];
            float wn = w[idx];
            float d2 = selv[r] + q2 + wn;     // = ||q - x||^2
            float f  = wn - sqrtf(fmaxf(d2, 0.0f));
            if (f > bestf) { bestf = f; besti = idx; }
        }
        out[b]      = bestf;
        out[NQ + b] = (float)besti;
    }
}

extern "C" void kernel_launch(void* const* d_in, const int* in_sizes, int n_in,
                              void* d_out, int out_size) {
    const float* q = (const float*)d_in[0];   // x_tilde [2048,128]
    const float* X = (const float*)d_in[1];   // X [100000,128]
    const float* w = (const float*)d_in[2];   // w [100000,1]
    float* out = (float*)d_out;               // [D_out(2048) | I_out(2048)] f32

    prep_kernel<<<(ND + NQ + 7) / 8, 256>>>(X, w, q);
    dim3 g(NQ / BM, (ND + BN - 1) / BN);      // (16, 782): m fastest for L2 reuse of X
    gemm_kernel<<<g, 256>>>(q, X);
    select_kernel<<<NQ, 256>>>(w, out);
}

// round 3
// speedup vs baseline: 1.7957x; 1.7957x over previous
#include <cuda_runtime.h>
#include <cuda_fp16.h>
#include <cstdint>

#define NQ   2048
#define ND   100000
#define NDP  100096          // 782 * 128
#define DIM  128
#define KSEL 10

// ---------------- scratch (static __device__: the sanctioned no-alloc path) ----
__device__ float  g_q2[NQ];
__device__ float  g_x2w[NDP];                   // ||x||^2 - w  (pad rows = +inf)
__device__ __half g_Ah[NQ * DIM];               // fp16-hi of (-2 * x_tilde)
__device__ __half g_Al[NQ * DIM];               // fp16-lo residual
__device__ __half g_Xh[(size_t)NDP * DIM];      // fp16-hi of X (pad rows = 0)
__device__ __half g_Xl[(size_t)NDP * DIM];
__device__ float  g_s[(size_t)NQ * NDP];        // score matrix

__device__ __forceinline__ uint32_t smem_u32(const void* p) {
    uint32_t a;
    asm("{ .reg .u64 t; cvta.to.shared.u64 t, %1; cvt.u32.u64 %0, t; }" : "=r"(a) : "l"(p));
    return a;
}
__device__ __forceinline__ void ldsm4(uint32_t* r, uint32_t addr) {
    asm volatile("ldmatrix.sync.aligned.m8n8.x4.shared.b16 {%0,%1,%2,%3}, [%4];"
        : "=r"(r[0]), "=r"(r[1]), "=r"(r[2]), "=r"(r[3]) : "r"(addr));
}
__device__ __forceinline__ void mma16816(float* c, const uint32_t* a, const uint32_t* b) {
    asm volatile("mma.sync.aligned.m16n8k16.row.col.f32.f16.f16.f32 "
        "{%0,%1,%2,%3}, {%4,%5,%6,%7}, {%8,%9}, {%0,%1,%2,%3};"
        : "+f"(c[0]), "+f"(c[1]), "+f"(c[2]), "+f"(c[3])
        : "r"(a[0]), "r"(a[1]), "r"(a[2]), "r"(a[3]), "r"(b[0]), "r"(b[1]));
}
// swizzled 16B-chunk index within a 256B row (16 chunks); XOR low3 with row&7
__device__ __forceinline__ uint32_t swzc(uint32_t ck, uint32_t s) {
    return ((ck ^ s) & 7u) | (ck & 8u);
}

// ---------------------------------------------------------------------------
// Kernel 1: norms + fp16 hi/lo splits (q scaled by -2, X padded to NDP).
// One warp per row.
// ---------------------------------------------------------------------------
__global__ void prep_kernel(const float* __restrict__ X,
                            const float* __restrict__ w,
                            const float* __restrict__ q) {
    int gw   = (blockIdx.x * 256 + threadIdx.x) >> 5;
    int lane = threadIdx.x & 31;
    if (gw < NDP) {
        if (gw < ND) {
            float4 v = reinterpret_cast<const float4*>(X + (size_t)gw * DIM)[lane];
            float s = v.x * v.x + v.y * v.y + v.z * v.z + v.w * v.w;
            #pragma unroll
            for (int o = 16; o > 0; o >>= 1) s += __shfl_xor_sync(0xffffffffu, s, o);
            float vv[4] = {v.x, v.y, v.z, v.w};
            __half h[4], l[4];
            #pragma unroll
            for (int i = 0; i < 4; i++) {
                h[i] = __float2half_rn(vv[i]);
                l[i] = __float2half_rn(vv[i] - __half2float(h[i]));
            }
            __half2* dh = reinterpret_cast<__half2*>(g_Xh + (size_t)gw * DIM + lane * 4);
            __half2* dl = reinterpret_cast<__half2*>(g_Xl + (size_t)gw * DIM + lane * 4);
            dh[0] = __halves2half2(h[0], h[1]); dh[1] = __halves2half2(h[2], h[3]);
            dl[0] = __halves2half2(l[0], l[1]); dl[1] = __halves2half2(l[2], l[3]);
            if (lane == 0) g_x2w[gw] = s - w[gw];
        } else {
            __half2 z = __halves2half2(__float2half(0.f), __float2half(0.f));
            __half2* dh = reinterpret_cast<__half2*>(g_Xh + (size_t)gw * DIM + lane * 4);
            __half2* dl = reinterpret_cast<__half2*>(g_Xl + (size_t)gw * DIM + lane * 4);
            dh[0] = z; dh[1] = z; dl[0] = z; dl[1] = z;
            if (lane == 0) g_x2w[gw] = __int_as_float(0x7f800000);  // +inf
        }
    } else if (gw < NDP + NQ) {
        int r = gw - NDP;
        float4 v = reinterpret_cast<const float4*>(q + (size_t)r * DIM)[lane];
        float s = v.x * v.x + v.y * v.y + v.z * v.z + v.w * v.w;
        #pragma unroll
        for (int o = 16; o > 0; o >>= 1) s += __shfl_xor_sync(0xffffffffu, s, o);
        if (lane == 0) g_q2[r] = s;
        float vv[4] = {-2.f * v.x, -2.f * v.y, -2.f * v.z, -2.f * v.w};
        __half h[4], l[4];
        #pragma unroll
        for (int i = 0; i < 4; i++) {
            h[i] = __float2half_rn(vv[i]);
            l[i] = __float2half_rn(vv[i] - __half2float(h[i]));
        }
        __half2* dh = reinterpret_cast<__half2*>(g_Ah + (size_t)r * DIM + lane * 4);
        __half2* dl = reinterpret_cast<__half2*>(g_Al + (size_t)r * DIM + lane * 4);
        dh[0] = __halves2half2(h[0], h[1]); dh[1] = __halves2half2(h[2], h[3]);
        dl[0] = __halves2half2(l[0], l[1]); dl[1] = __halves2half2(l[2], l[3]);
    }
}

// ---------------------------------------------------------------------------
// Kernel 2: fp16-split HMMA GEMM.  s[m, n] = (-2q_m) . x_n + x2w[n]
// CTA = 128x128 output tile, full K=128 resident in smem, 8 warps (2m x 4n).
// Terms: Ah*Bh + Ah*Bl + Al*Bh  (Al*Bl ~ 2^-22, dropped)
// ---------------------------------------------------------------------------
#define TILE_HB 32768                 // 128 rows x 256B (128 halves)
#define SA_H 0
#define SA_L 32768
#define SB_H 65536
#define SB_L 98304
#define SX2  131072                   // 128 floats
#define SMEM_TOTAL (131072 + 512)

__global__ void __launch_bounds__(256, 1)
gemm_hmma_kernel() {
    extern __shared__ char smem[];
    const uint32_t sb = smem_u32(smem);
    const int t = threadIdx.x, lane = t & 31, wid = t >> 5;
    const int m0 = blockIdx.x * 128, n0 = blockIdx.y * 128;
    const int wm = (wid >> 2) * 64, wn = (wid & 3) * 32;

    if (t < 128) reinterpret_cast<float*>(smem + SX2)[t] = g_x2w[n0 + t];

    // stage 4 tiles: 2048 float4 each, swizzled
    #pragma unroll
    for (int i = 0; i < 32; i++) {
        int id     = t + 256 * i;
        int tile   = id >> 11;
        int within = id & 2047;
        int row    = within >> 4;
        int c      = within & 15;
        const __half* src = (tile == 0) ? g_Ah : (tile == 1) ? g_Al
                          : (tile == 2) ? g_Xh : g_Xl;
        int grow = ((tile < 2) ? m0 : n0) + row;
        float4 v = *reinterpret_cast<const float4*>(
            reinterpret_cast<const char*>(src) + (size_t)grow * 256 + c * 16);
        uint32_t cp = swzc((uint32_t)c, (uint32_t)(row & 7));
        *reinterpret_cast<float4*>(smem + tile * TILE_HB + row * 256 + cp * 16) = v;
    }
    __syncthreads();

    // per-thread ldmatrix row addresses
    uint32_t aOff[4], aS[4];
    #pragma unroll
    for (int mf = 0; mf < 4; mf++) {
        int r = wm + mf * 16 + (lane & 15);
        aOff[mf] = (uint32_t)r * 256; aS[mf] = r & 7;
    }
    uint32_t bOff[2], bS[2];
    #pragma unroll
    for (int p = 0; p < 2; p++) {
        int r = wn + p * 16 + (lane & 7) + ((lane >> 4) << 3);
        bOff[p] = (uint32_t)r * 256; bS[p] = r & 7;
    }
    const uint32_t aHi = (lane >> 4) & 1;       // chunk +1 for lanes 16-31 (A)
    const uint32_t bHi = (lane >> 3) & 1;       // chunk +1 for lanes 8-15/24-31 (B)

    float acc[4][4][4];
    #pragma unroll
    for (int mf = 0; mf < 4; mf++)
        #pragma unroll
        for (int nf = 0; nf < 4; nf++)
            #pragma unroll
            for (int e = 0; e < 4; e++) acc[mf][nf][e] = 0.f;

    #pragma unroll
    for (int c8 = 0; c8 < 8; c8++) {
        uint32_t ah[4][4], al[4][4], bh[2][4], bl[2][4];
        uint32_t ckA = 2 * c8 + aHi;
        uint32_t ckB = 2 * c8 + bHi;
        #pragma unroll
        for (int mf = 0; mf < 4; mf++) {
            ldsm4(ah[mf], sb + SA_H + aOff[mf] + swzc(ckA, aS[mf]) * 16);
            ldsm4(al[mf], sb + SA_L + aOff[mf] + swzc(ckA, aS[mf]) * 16);
        }
        #pragma unroll
        for (int p = 0; p < 2; p++) {
            ldsm4(bh[p], sb + SB_H + bOff[p] + swzc(ckB, bS[p]) * 16);
            ldsm4(bl[p], sb + SB_L + bOff[p] + swzc(ckB, bS[p]) * 16);
        }
        #pragma unroll
        for (int mf = 0; mf < 4; mf++)
            #pragma unroll
            for (int nf = 0; nf < 4; nf++) {
                int p = nf >> 1, pr = (nf & 1) * 2;
                mma16816(acc[mf][nf], ah[mf], &bh[p][pr]);
                mma16816(acc[mf][nf], ah[mf], &bl[p][pr]);
                mma16816(acc[mf][nf], al[mf], &bh[p][pr]);
            }
    }

    // epilogue: + x2w, streaming store
    const int g = lane >> 2, tig = lane & 3;
    #pragma unroll
    for (int mf = 0; mf < 4; mf++) {
        int m = m0 + wm + mf * 16 + g;
        #pragma unroll
        for (int nf = 0; nf < 4; nf++) {
            int nl = wn + nf * 8 + tig * 2;
            float2 xw = *reinterpret_cast<const float2*>(smem + SX2 + nl * 4);
            float2 v0, v1;
            v0.x = acc[mf][nf][0] + xw.x; v0.y = acc[mf][nf][1] + xw.y;
            v1.x = acc[mf][nf][2] + xw.x; v1.y = acc[mf][nf][3] + xw.y;
            __stcs(reinterpret_cast<float2*>(g_s + (size_t)m * NDP + n0 + nl), v0);
            __stcs(reinterpret_cast<float2*>(g_s + (size_t)(m + 8) * NDP + n0 + nl), v1);
        }
    }
}

// ---------------------------------------------------------------------------
// Kernel 3: per-query top-10 + final activation argmax.
// ---------------------------------------------------------------------------
__global__ void __launch_bounds__(256, 1)
select_kernel(const float* __restrict__ w, float* __restrict__ out) {
    const int b = blockIdx.x;
    const int t = threadIdx.x;
    const float4* row4 = reinterpret_cast<const float4*>(g_s + (size_t)b * NDP);

    float bv[KSEL];
    int   bi[KSEL];
    #pragma unroll
    for (int r = 0; r < KSEL; r++) { bv[r] = __int_as_float(0x7f800000); bi[r] = 0; }

    // paired loads for MLP=2  (NDP/4 = 25024 is even)
    for (int j4 = t * 2; j4 < NDP / 4; j4 += 512) {
        float4 v0 = __ldcs(&row4[j4]);
        float4 v1 = __ldcs(&row4[j4 + 1]);
        float vv[8] = {v0.x, v0.y, v0.z, v0.w, v1.x, v1.y, v1.z, v1.w};
        int n = j4 * 4;
        #pragma unroll
        for (int e = 0; e < 8; e++) {
            float x = vv[e];
            if (x < bv[KSEL - 1]) {
                float cv = x; int ci = n + e;
                #pragma unroll
                for (int r = 0; r < KSEL; r++) {
                    if (cv < bv[r]) {
                        float tv = bv[r]; bv[r] = cv; cv = tv;
                        int ti = bi[r]; bi[r] = ci; ci = ti;
                    }
                }
            }
        }
    }

    __shared__ float sv[256 * (KSEL + 1)];
    __shared__ int   si[256 * (KSEL + 1)];
    __shared__ float redv[256];
    __shared__ int   redt[256];
    __shared__ float selv[KSEL];
    __shared__ int   seli[KSEL];

    #pragma unroll
    for (int r = 0; r < KSEL; r++) {
        sv[t * (KSEL + 1) + r] = bv[r];
        si[t * (KSEL + 1) + r] = bi[r];
    }
    sv[t * (KSEL + 1) + KSEL] = __int_as_float(0x7f800000);
    __syncthreads();

    int h = 0;
    for (int r = 0; r < KSEL; r++) {
        redv[t] = sv[t * (KSEL + 1) + h];
        redt[t] = t;
        __syncthreads();
        #pragma unroll
        for (int s = 128; s > 0; s >>= 1) {
            if (t < s) {
                if (redv[t + s] < redv[t]) { redv[t] = redv[t + s]; redt[t] = redt[t + s]; }
            }
            __syncthreads();
        }
        if (t == redt[0]) {
            selv[r] = sv[t * (KSEL + 1) + h];
            seli[r] = si[t * (KSEL + 1) + h];
            h++;
        }
        __syncthreads();
    }

    if (t == 0) {
        float q2 = g_q2[b];
        float bestf = __int_as_float(0xff800000);
        int besti = 0;
        #pragma unroll
        for (int r = 0; r < KSEL; r++) {
            int idx = seli[r];
            float wn = w[idx];
            float d2 = selv[r] + q2 + wn;       // ||q - x||^2
            float f  = wn - sqrtf(fmaxf(d2, 0.0f));
            if (f > bestf) { bestf = f; besti = idx; }
        }
        out[b]      = bestf;
        out[NQ + b] = (float)besti;
    }
}

extern "C" void kernel_launch(void* const* d_in, const int* in_sizes, int n_in,
                              void* d_out, int out_size) {
    const float* q = (const float*)d_in[0];   // x_tilde [2048,128]
    const float* X = (const float*)d_in[1];   // X [100000,128]
    const float* w = (const float*)d_in[2];   // w [100000,1]
    float* out = (float*)d_out;

    cudaFuncSetAttribute(gemm_hmma_kernel,
                         cudaFuncAttributeMaxDynamicSharedMemorySize, SMEM_TOTAL);

    prep_kernel<<<(NDP + NQ) / 8, 256>>>(X, w, q);
    dim3 g(NQ / 128, NDP / 128);              // (16, 782): m fastest for L2 X reuse
    gemm_hmma_kernel<<<g, 256, SMEM_TOTAL>>>();
    select_kernel<<<NQ, 256>>>(w, out);
}